// round 10
// baseline (speedup 1.0000x reference)
#include <cuda_runtime.h>
#include <cuda_fp16.h>
#include <math.h>

#define Bb 16
#define Hh 512
#define Ww 512
#define HW (Hh*Ww)
#define BHW (Bb*HW)
#define Lsteps 10

// ---- scratch in device globals (no allocation allowed) ----
__device__ float   d_res[10 * BHW];     // residuals[1..10] fp32 master (slot k = residuals[k+1])
__device__ __half  d_res16[10 * BHW];   // fp16 shadow for gathers
__device__ __half2 d_uA[10 * BHW];      // phi displacement ping (u = phi - id)
__device__ __half2 d_uB[10 * BHW];      // phi displacement pong
__device__ float   d_img[BHW];          // current image

// 7-tap gaussian, sigma=2 (normalized)
__device__ __constant__ float GW[7] = {
    0.070159329f, 0.131074882f, 0.190712821f, 0.216105908f,
    0.190712821f, 0.131074882f, 0.070159329f
};

#define TX 32
#define TY 32
#define IMW 42
#define IMH 42
#define RW  40
#define RH  40
#define TW  34
#define TH  40
#define VW  34
#define VH  34
#define POOL 6564

// Fused velocity: grad -> a=-res*grad -> blurH -> blurV=v -> div -> res_next, u=-v/L
__global__ __launch_bounds__(256, 7) void k_vel(const float* __restrict__ img,
                                                const float* __restrict__ res,
                                                float* __restrict__ res_next,
                                                __half* __restrict__ res16out,
                                                __half2* __restrict__ uA,
                                                __half2* __restrict__ uB) {
    __shared__ __align__(16) float pool[POOL];
    float*   s_res = pool;
    float2*  s_a   = (float2*)(pool + 1600);
    float2*  s_v   = (float2*)(pool + 1600);
    float*   s_img = pool + 4800;
    __half2* s_t   = (__half2*)(pool + 4800);

    const int b  = blockIdx.z;
    const int X0 = blockIdx.x * TX;
    const int Y0 = blockIdx.y * TY;
    const float* ip = img + (size_t)b * HW;
    const float* rp = res + (size_t)b * HW;
    const int t = threadIdx.x;

    for (int k = t; k < IMH * IMW; k += 256) {
        int ly = k / IMW, lx = k % IMW;
        int gy = min(max(Y0 - 5 + ly, 0), Hh - 1);
        int gx = min(max(X0 - 5 + lx, 0), Ww - 1);
        s_img[k] = ip[gy * Ww + gx];
    }
    for (int k = t; k < RH * RW; k += 256) {
        int ly = k / RW, lx = k % RW;
        int gy = Y0 - 4 + ly, gx = X0 - 4 + lx;
        s_res[k] = (gy >= 0 && gy < Hh && gx >= 0 && gx < Ww) ? rp[gy * Ww + gx] : 0.f;
    }
    __syncthreads();

    for (int k = t; k < RH * RW; k += 256) {
        int ly = k / RW, lx = k % RW;
        float2 a = make_float2(0.f, 0.f);
        float r = s_res[k];
        if (r != 0.f) {
            const float* c = &s_img[(ly + 1) * IMW + (lx + 1)];
            float Imm = c[-IMW - 1], Im0 = c[-IMW], Imp = c[-IMW + 1];
            float I0m = c[-1],                        I0p = c[1];
            float Ipm = c[IMW - 1],  Ip0 = c[IMW],  Ipp = c[IMW + 1];
            float gxv = (-Imm + Imp - 2.f * I0m + 2.f * I0p - Ipm + Ipp) * 0.125f;
            float gyv = (-Imm - 2.f * Im0 - Imp + Ipm + 2.f * Ip0 + Ipp) * 0.125f;
            a.x = -r * gxv;
            a.y = -r * gyv;
        }
        s_a[k] = a;
    }
    __syncthreads();

    for (int k = t; k < TH * TW; k += 256) {
        int ly = k / TW, lx = k % TW;
        const float2* ap = &s_a[ly * RW + lx];
        float s0 = 0.f, s1 = 0.f;
        #pragma unroll
        for (int kk = 0; kk < 7; kk++) {
            float2 av = ap[kk];
            s0 += GW[kk] * av.x;
            s1 += GW[kk] * av.y;
        }
        s_t[k] = __floats2half2_rn(s0, s1);
    }
    __syncthreads();

    for (int k = t; k < VH * VW; k += 256) {
        int ly = k / VW, lx = k % VW;
        const __half2* tp = &s_t[ly * TW + lx];
        float s0 = 0.f, s1 = 0.f;
        #pragma unroll
        for (int kk = 0; kk < 7; kk++) {
            float2 tv = __half22float2(tp[kk * TW]);
            s0 += GW[kk] * tv.x;
            s1 += GW[kk] * tv.y;
        }
        s_v[k] = make_float2(s0, s1);
    }
    __syncthreads();

    const float invL = 1.f / (float)Lsteps;
    for (int k = t; k < TX * TY; k += 256) {
        int ty = k / TX, tx = k % TX;
        int gy = Y0 + ty, gx = X0 + tx;
        int vi = (ty + 1) * VW + (tx + 1);
        int ri = (ty + 4) * RW + (tx + 4);
        float2 vmm = s_v[vi - VW - 1], vm0 = s_v[vi - VW], vmp = s_v[vi - VW + 1];
        float2 v0m = s_v[vi - 1],      v00 = s_v[vi],      v0p = s_v[vi + 1];
        float2 vpm = s_v[vi + VW - 1], vp0 = s_v[vi + VW], vpp = s_v[vi + VW + 1];
        float rmm = s_res[ri - RW - 1], rm0 = s_res[ri - RW], rmp = s_res[ri - RW + 1];
        float r0m = s_res[ri - 1],                             r0p = s_res[ri + 1];
        float rpm = s_res[ri + RW - 1], rp0 = s_res[ri + RW], rpp = s_res[ri + RW + 1];
        float f =
            (- rmm * vmm.x + rmp * vmp.x
             - 2.f * r0m * v0m.x + 2.f * r0p * v0p.x
             - rpm * vpm.x + rpp * vpp.x
             - rmm * vmm.y - 2.f * rm0 * vm0.y - rmp * vmp.y
             + rpm * vpm.y + 2.f * rp0 * vp0.y + rpp * vpp.y)
            * (0.125f / (float)Lsteps);
        int gidx = b * HW + gy * Ww + gx;
        float rv = s_res[ri] - f;
        res_next[gidx] = rv;
        res16out[gidx] = __float2half(rv);
        __half2 uh = __floats2half2_rn(-v00.x * invL, -v00.y * invL);
        uA[gidx] = uh;
        uB[gidx] = uh;
    }
}

// ---------- gather helpers ----------
__device__ __forceinline__ float2 gather_phi(const __half2* __restrict__ u, float px, float py) {
    float x0f = floorf(px), y0f = floorf(py);
    float wx = px - x0f, wy = py - y0f;
    int x0 = (int)x0f, y0 = (int)y0f;
    float w00 = (1.f - wx) * (1.f - wy), w10 = wx * (1.f - wy);
    float w01 = (1.f - wx) * wy,         w11 = wx * wy;
    if (x0 >= 0 && y0 >= 0 && x0 < Ww - 1 && y0 < Hh - 1) {
        const __half2* r0 = u + y0 * Ww + x0;
        float2 a = __half22float2(r0[0]);
        float2 bb = __half22float2(r0[1]);
        float2 c = __half22float2(r0[Ww]);
        float2 d = __half22float2(r0[Ww + 1]);
        float ux = a.x * w00 + bb.x * w10 + c.x * w01 + d.x * w11;
        float uy = a.y * w00 + bb.y * w10 + c.y * w01 + d.y * w11;
        return make_float2(px + ux, py + uy);
    }
    int x1 = x0 + 1, y1 = y0 + 1;
    float rx = 0.f, ry = 0.f;
    #define PHITAP(xt, yt, w) \
        if ((xt) >= 0 && (xt) < Ww && (yt) >= 0 && (yt) < Hh) { \
            float2 uu = __half22float2(u[(yt) * Ww + (xt)]); \
            rx += (w) * ((float)(xt) + uu.x); \
            ry += (w) * ((float)(yt) + uu.y); \
        }
    PHITAP(x0, y0, w00) PHITAP(x1, y0, w10) PHITAP(x0, y1, w01) PHITAP(x1, y1, w11)
    #undef PHITAP
    return make_float2(rx, ry);
}

__device__ __forceinline__ float gather_res16(const __half* __restrict__ p, float px, float py) {
    float x0f = floorf(px), y0f = floorf(py);
    float wx = px - x0f, wy = py - y0f;
    int x0 = (int)x0f, y0 = (int)y0f;
    float Ia, Ib, Ic, Id;
    if (x0 >= 0 && y0 >= 0 && x0 < Ww - 1 && y0 < Hh - 1) {
        const __half* r0 = p + y0 * Ww + x0;
        Ia = __half2float(r0[0]); Ib = __half2float(r0[1]);
        Ic = __half2float(r0[Ww]); Id = __half2float(r0[Ww + 1]);
    } else {
        int x1 = x0 + 1, y1 = y0 + 1;
        bool bx0 = (x0 >= 0) && (x0 < Ww), bx1 = (x1 >= 0) && (x1 < Ww);
        bool by0 = (y0 >= 0) && (y0 < Hh), by1 = (y1 >= 0) && (y1 < Hh);
        Ia = (bx0 && by0) ? __half2float(p[y0 * Ww + x0]) : 0.f;
        Ib = (bx1 && by0) ? __half2float(p[y0 * Ww + x1]) : 0.f;
        Ic = (bx0 && by1) ? __half2float(p[y1 * Ww + x0]) : 0.f;
        Id = (bx1 && by1) ? __half2float(p[y1 * Ww + x1]) : 0.f;
    }
    return Ia * (1.f - wx) * (1.f - wy) + Ib * wx * (1.f - wy)
         + Ic * (1.f - wx) * wy        + Id * wx * wy;
}

__device__ __forceinline__ float bilerp1(const float* __restrict__ p, float px, float py) {
    float x0f = floorf(px), y0f = floorf(py);
    float wx = px - x0f, wy = py - y0f;
    int x0 = (int)x0f, y0 = (int)y0f;
    float Ia, Ib, Ic, Id;
    if (x0 >= 0 && y0 >= 0 && x0 < Ww - 1 && y0 < Hh - 1) {
        const float* r0 = p + y0 * Ww + x0;
        Ia = r0[0]; Ib = r0[1]; Ic = r0[Ww]; Id = r0[Ww + 1];
    } else {
        int x1 = x0 + 1, y1 = y0 + 1;
        bool bx0 = (x0 >= 0) && (x0 < Ww), bx1 = (x1 >= 0) && (x1 < Ww);
        bool by0 = (y0 >= 0) && (y0 < Hh), by1 = (y1 >= 0) && (y1 < Hh);
        Ia = (bx0 && by0) ? p[y0 * Ww + x0] : 0.f;
        Ib = (bx1 && by0) ? p[y0 * Ww + x1] : 0.f;
        Ic = (bx0 && by1) ? p[y1 * Ww + x0] : 0.f;
        Id = (bx1 && by1) ? p[y1 * Ww + x1] : 0.f;
    }
    return Ia * (1.f - wx) * (1.f - wy) + Ib * wx * (1.f - wy)
         + Ic * (1.f - wx) * wy        + Id * wx * wy;
}

// Templated on step index I -> j-loop fully unrolled, all gathers batched (MLP ~4I).
template<int I>
__global__ __launch_bounds__(256, 7) void k_warpfinal(const __half2* __restrict__ srcu,
                            __half2* __restrict__ dstu,
                            const float* __restrict__ res32,
                            const __half* __restrict__ res16,
                            const float* __restrict__ srcimg,
                            const float* __restrict__ seg,
                            float* __restrict__ out) {
    int idx = blockIdx.x * blockDim.x + threadIdx.x;
    if (idx >= BHW) return;
    int x = idx & (Ww - 1);
    int y = (idx >> 9) & (Hh - 1);
    int base = idx - (y << 9) - x;
    float fx = (float)x, fy = (float)y;

    float2 ui = __half22float2(srcu[(size_t)I * BHW + idx]);
    float2 pd = make_float2(fx + ui.x, fy + ui.y);

    float acc = res32[(size_t)I * BHW + idx];
    float2 p0 = pd;

    // Phase A: all phi gathers (independent; unrolled -> batched LDGs)
    float2 warped[I > 0 ? I : 1];
    #pragma unroll
    for (int j = 0; j < I; j++)
        warped[j] = gather_phi(srcu + (size_t)j * BHW + base, pd.x, pd.y);

    // Phase B: stores + residual gathers (also unrolled/batched)
    #pragma unroll
    for (int j = 0; j < I; j++) {
        dstu[(size_t)j * BHW + idx] = __floats2half2_rn(warped[j].x - fx, warped[j].y - fy);
        if (j == 0) p0 = warped[0];
        else acc += gather_res16(res16 + (size_t)(j - 1) * BHW + base, warped[j].x, warped[j].y);
    }
    if (I >= 1) acc += gather_res16(res16 + (size_t)(I - 1) * BHW + base, pd.x, pd.y);

    float s = bilerp1(srcimg + base, p0.x, p0.y);
    float m = bilerp1(seg + base, p0.x, p0.y);
    const float scale = 2.5e-4f;  // MU^2 / L
    out[idx] = s + acc * scale * m;
}

extern "C" void kernel_launch(void* const* d_in, const int* in_sizes, int n_in,
                              void* d_out, int out_size) {
    const float* src = (const float*)d_in[0];
    const float* z0  = (const float*)d_in[1];
    const float* seg = (const float*)d_in[2];

    float*   res;   cudaGetSymbolAddress((void**)&res,   d_res);
    __half*  res16; cudaGetSymbolAddress((void**)&res16, d_res16);
    __half2* uA;    cudaGetSymbolAddress((void**)&uA,    d_uA);
    __half2* uB;    cudaGetSymbolAddress((void**)&uB,    d_uB);
    float*   img;   cudaGetSymbolAddress((void**)&img,   d_img);

    const int threads = 256;
    const int blocks = BHW / threads;
    dim3 vgrid(Ww / TX, Hh / TY, Bb);

    for (int i = 0; i < Lsteps; i++) {
        const float* img_in = (i == 0) ? src : img;
        const float* res_i  = (i == 0) ? z0  : res + (size_t)(i - 1) * BHW;

        k_vel<<<vgrid, 256>>>(img_in, res_i, res + (size_t)i * BHW,
                              res16 + (size_t)i * BHW,
                              uA + (size_t)i * BHW, uB + (size_t)i * BHW);

        __half2* dst = (i & 1) ? uB : uA;
        const __half2* s2 = (i & 1) ? uA : uB;
        float* outp = (i == Lsteps - 1) ? (float*)d_out : img;

        switch (i) {
            case 0: k_warpfinal<0><<<blocks, threads>>>(s2, dst, res, res16, src, seg, outp); break;
            case 1: k_warpfinal<1><<<blocks, threads>>>(s2, dst, res, res16, src, seg, outp); break;
            case 2: k_warpfinal<2><<<blocks, threads>>>(s2, dst, res, res16, src, seg, outp); break;
            case 3: k_warpfinal<3><<<blocks, threads>>>(s2, dst, res, res16, src, seg, outp); break;
            case 4: k_warpfinal<4><<<blocks, threads>>>(s2, dst, res, res16, src, seg, outp); break;
            case 5: k_warpfinal<5><<<blocks, threads>>>(s2, dst, res, res16, src, seg, outp); break;
            case 6: k_warpfinal<6><<<blocks, threads>>>(s2, dst, res, res16, src, seg, outp); break;
            case 7: k_warpfinal<7><<<blocks, threads>>>(s2, dst, res, res16, src, seg, outp); break;
            case 8: k_warpfinal<8><<<blocks, threads>>>(s2, dst, res, res16, src, seg, outp); break;
            case 9: k_warpfinal<9><<<blocks, threads>>>(s2, dst, res, res16, src, seg, outp); break;
        }
    }
}

// round 11
// speedup vs baseline: 1.0761x; 1.0761x over previous
#include <cuda_runtime.h>
#include <cuda_fp16.h>
#include <math.h>

#define Bb 16
#define Hh 512
#define Ww 512
#define HW (Hh*Ww)
#define BHW (Bb*HW)
#define Lsteps 10

// ---- scratch in device globals (no allocation allowed) ----
__device__ float   d_res[10 * BHW];     // residuals[1..10] fp32 master (slot k = residuals[k+1])
__device__ __half  d_res16[10 * BHW];   // fp16 shadow for gathers
__device__ __half2 d_uA[10 * BHW];      // phi displacement ping (u = phi - id)
__device__ __half2 d_uB[10 * BHW];      // phi displacement pong
__device__ float   d_img[BHW];          // current image

#define TX 32
#define TY 32
#define IMW 42
#define IMH 42
#define RW  40
#define RH  40
#define TW  34
#define TH  40
#define VW  34
#define VH  34
#define POOL 6564

// Fused velocity: grad -> a=-res*grad -> blurH -> blurV=v -> div -> res_next, u=-v/L
__global__ __launch_bounds__(256, 7) void k_vel(const float* __restrict__ img,
                                                const float* __restrict__ res,
                                                float* __restrict__ res_next,
                                                __half* __restrict__ res16out,
                                                __half2* __restrict__ uA,
                                                __half2* __restrict__ uB) {
    __shared__ __align__(16) float pool[POOL];
    float*   s_res = pool;
    float2*  s_a   = (float2*)(pool + 1600);
    float2*  s_v   = (float2*)(pool + 1600);
    float*   s_img = pool + 4800;
    __half2* s_t   = (__half2*)(pool + 4800);

    const float gw[7] = {0.070159329f, 0.131074882f, 0.190712821f, 0.216105908f,
                         0.190712821f, 0.131074882f, 0.070159329f};

    const int b  = blockIdx.z;
    const int X0 = blockIdx.x * TX;
    const int Y0 = blockIdx.y * TY;
    const float* ip = img + (size_t)b * HW;
    const float* rp = res + (size_t)b * HW;
    const int t = threadIdx.x;

    // ---- stage img (42x42, replicate). step: dl=6, dx=4 (256 = 6*42+4) ----
    {
        int ly = t / IMW, lx = t - ly * IMW;
        for (int k = t; k < IMH * IMW; k += 256) {
            int gy = min(max(Y0 - 5 + ly, 0), Hh - 1);
            int gx = min(max(X0 - 5 + lx, 0), Ww - 1);
            s_img[k] = ip[gy * Ww + gx];
            lx += 4; ly += 6; if (lx >= IMW) { lx -= IMW; ly += 1; }
        }
    }
    // ---- stage res (40x40, zero-pad). step: dl=6, dx=16 (256 = 6*40+16) ----
    {
        int ly = t / RW, lx = t - ly * RW;
        for (int k = t; k < RH * RW; k += 256) {
            int gy = Y0 - 4 + ly, gx = X0 - 4 + lx;
            s_res[k] = (gy >= 0 && gy < Hh && gx >= 0 && gx < Ww) ? rp[gy * Ww + gx] : 0.f;
            lx += 16; ly += 6; if (lx >= RW) { lx -= RW; ly += 1; }
        }
    }
    __syncthreads();

    // ---- a = -res * sobel(img) over 40x40 ----
    {
        int ly = t / RW, lx = t - ly * RW;
        for (int k = t; k < RH * RW; k += 256) {
            float2 a = make_float2(0.f, 0.f);
            float r = s_res[k];
            if (r != 0.f) {
                const float* c = &s_img[(ly + 1) * IMW + (lx + 1)];
                float Imm = c[-IMW - 1], Im0 = c[-IMW], Imp = c[-IMW + 1];
                float I0m = c[-1],                        I0p = c[1];
                float Ipm = c[IMW - 1],  Ip0 = c[IMW],  Ipp = c[IMW + 1];
                float gxv = (-Imm + Imp - 2.f * I0m + 2.f * I0p - Ipm + Ipp) * 0.125f;
                float gyv = (-Imm - 2.f * Im0 - Imp + Ipm + 2.f * Ip0 + Ipp) * 0.125f;
                a.x = -r * gxv;
                a.y = -r * gyv;
            }
            s_a[k] = a;
            lx += 16; ly += 6; if (lx >= RW) { lx -= RW; ly += 1; }
        }
    }
    __syncthreads();

    // ---- blurH: 40x34 -> t (half2). step for W=34: dl=7, dx=18 (256 = 7*34+18) ----
    {
        int ly = t / TW, lx = t - ly * TW;
        for (int k = t; k < TH * TW; k += 256) {
            const float2* ap = &s_a[ly * RW + lx];
            float s0 = 0.f, s1 = 0.f;
            #pragma unroll
            for (int kk = 0; kk < 7; kk++) {
                float2 av = ap[kk];
                s0 += gw[kk] * av.x;
                s1 += gw[kk] * av.y;
            }
            s_t[k] = __floats2half2_rn(s0, s1);
            lx += 18; ly += 7; if (lx >= TW) { lx -= TW; ly += 1; }
        }
    }
    __syncthreads();

    // ---- blurV: 34x34 -> v (float2). index identity: ly*TW+lx == k ----
    for (int k = t; k < VH * VW; k += 256) {
        const __half2* tp = &s_t[k];
        float s0 = 0.f, s1 = 0.f;
        #pragma unroll
        for (int kk = 0; kk < 7; kk++) {
            float2 tv = __half22float2(tp[kk * TW]);
            s0 += gw[kk] * tv.x;
            s1 += gw[kk] * tv.y;
        }
        s_v[k] = make_float2(s0, s1);
    }
    __syncthreads();

    // ---- div -> res_next; u = -v/L. 32x32 outputs (pow2 indexing) ----
    const float invL = 1.f / (float)Lsteps;
    for (int k = t; k < TX * TY; k += 256) {
        int ty = k >> 5, tx = k & 31;
        int gy = Y0 + ty, gx = X0 + tx;
        int vi = (ty + 1) * VW + (tx + 1);
        int ri = (ty + 4) * RW + (tx + 4);
        float2 vmm = s_v[vi - VW - 1], vm0 = s_v[vi - VW], vmp = s_v[vi - VW + 1];
        float2 v0m = s_v[vi - 1],      v00 = s_v[vi],      v0p = s_v[vi + 1];
        float2 vpm = s_v[vi + VW - 1], vp0 = s_v[vi + VW], vpp = s_v[vi + VW + 1];
        float rmm = s_res[ri - RW - 1], rm0 = s_res[ri - RW], rmp = s_res[ri - RW + 1];
        float r0m = s_res[ri - 1],                             r0p = s_res[ri + 1];
        float rpm = s_res[ri + RW - 1], rp0 = s_res[ri + RW], rpp = s_res[ri + RW + 1];
        float f =
            (- rmm * vmm.x + rmp * vmp.x
             - 2.f * r0m * v0m.x + 2.f * r0p * v0p.x
             - rpm * vpm.x + rpp * vpp.x
             - rmm * vmm.y - 2.f * rm0 * vm0.y - rmp * vmp.y
             + rpm * vpm.y + 2.f * rp0 * vp0.y + rpp * vpp.y)
            * (0.125f / (float)Lsteps);
        int gidx = b * HW + gy * Ww + gx;
        float rv = s_res[ri] - f;
        res_next[gidx] = rv;
        res16out[gidx] = __float2half(rv);
        __half2 uh = __floats2half2_rn(-v00.x * invL, -v00.y * invL);
        uA[gidx] = uh;
        uB[gidx] = uh;
    }
}

// ---------- gather helpers ----------
__device__ __forceinline__ float2 gather_phi(const __half2* __restrict__ u, float px, float py) {
    float x0f = floorf(px), y0f = floorf(py);
    float wx = px - x0f, wy = py - y0f;
    int x0 = (int)x0f, y0 = (int)y0f;
    float w00 = (1.f - wx) * (1.f - wy), w10 = wx * (1.f - wy);
    float w01 = (1.f - wx) * wy,         w11 = wx * wy;
    if (x0 >= 0 && y0 >= 0 && x0 < Ww - 1 && y0 < Hh - 1) {
        const __half2* r0 = u + y0 * Ww + x0;
        float2 a = __half22float2(r0[0]);
        float2 bb = __half22float2(r0[1]);
        float2 c = __half22float2(r0[Ww]);
        float2 d = __half22float2(r0[Ww + 1]);
        float ux = a.x * w00 + bb.x * w10 + c.x * w01 + d.x * w11;
        float uy = a.y * w00 + bb.y * w10 + c.y * w01 + d.y * w11;
        return make_float2(px + ux, py + uy);
    }
    int x1 = x0 + 1, y1 = y0 + 1;
    float rx = 0.f, ry = 0.f;
    #define PHITAP(xt, yt, w) \
        if ((xt) >= 0 && (xt) < Ww && (yt) >= 0 && (yt) < Hh) { \
            float2 uu = __half22float2(u[(yt) * Ww + (xt)]); \
            rx += (w) * ((float)(xt) + uu.x); \
            ry += (w) * ((float)(yt) + uu.y); \
        }
    PHITAP(x0, y0, w00) PHITAP(x1, y0, w10) PHITAP(x0, y1, w01) PHITAP(x1, y1, w11)
    #undef PHITAP
    return make_float2(rx, ry);
}

__device__ __forceinline__ float gather_res16(const __half* __restrict__ p, float px, float py) {
    float x0f = floorf(px), y0f = floorf(py);
    float wx = px - x0f, wy = py - y0f;
    int x0 = (int)x0f, y0 = (int)y0f;
    float Ia, Ib, Ic, Id;
    if (x0 >= 0 && y0 >= 0 && x0 < Ww - 1 && y0 < Hh - 1) {
        const __half* r0 = p + y0 * Ww + x0;
        Ia = __half2float(r0[0]); Ib = __half2float(r0[1]);
        Ic = __half2float(r0[Ww]); Id = __half2float(r0[Ww + 1]);
    } else {
        int x1 = x0 + 1, y1 = y0 + 1;
        bool bx0 = (x0 >= 0) && (x0 < Ww), bx1 = (x1 >= 0) && (x1 < Ww);
        bool by0 = (y0 >= 0) && (y0 < Hh), by1 = (y1 >= 0) && (y1 < Hh);
        Ia = (bx0 && by0) ? __half2float(p[y0 * Ww + x0]) : 0.f;
        Ib = (bx1 && by0) ? __half2float(p[y0 * Ww + x1]) : 0.f;
        Ic = (bx0 && by1) ? __half2float(p[y1 * Ww + x0]) : 0.f;
        Id = (bx1 && by1) ? __half2float(p[y1 * Ww + x1]) : 0.f;
    }
    return Ia * (1.f - wx) * (1.f - wy) + Ib * wx * (1.f - wy)
         + Ic * (1.f - wx) * wy        + Id * wx * wy;
}

__device__ __forceinline__ float bilerp1(const float* __restrict__ p, float px, float py) {
    float x0f = floorf(px), y0f = floorf(py);
    float wx = px - x0f, wy = py - y0f;
    int x0 = (int)x0f, y0 = (int)y0f;
    float Ia, Ib, Ic, Id;
    if (x0 >= 0 && y0 >= 0 && x0 < Ww - 1 && y0 < Hh - 1) {
        const float* r0 = p + y0 * Ww + x0;
        Ia = r0[0]; Ib = r0[1]; Ic = r0[Ww]; Id = r0[Ww + 1];
    } else {
        int x1 = x0 + 1, y1 = y0 + 1;
        bool bx0 = (x0 >= 0) && (x0 < Ww), bx1 = (x1 >= 0) && (x1 < Ww);
        bool by0 = (y0 >= 0) && (y0 < Hh), by1 = (y1 >= 0) && (y1 < Hh);
        Ia = (bx0 && by0) ? p[y0 * Ww + x0] : 0.f;
        Ib = (bx1 && by0) ? p[y0 * Ww + x1] : 0.f;
        Ic = (bx0 && by1) ? p[y1 * Ww + x0] : 0.f;
        Id = (bx1 && by1) ? p[y1 * Ww + x1] : 0.f;
    }
    return Ia * (1.f - wx) * (1.f - wy) + Ib * wx * (1.f - wy)
         + Ic * (1.f - wx) * wy        + Id * wx * wy;
}

// Fused: warp all stored phis through D_i (sampled at pd = D_i(x)), store
// warped displacements, gather residuals, update image. (R9 generic form.)
__global__ __launch_bounds__(256, 7) void k_warpfinal(int i, const __half2* __restrict__ srcu,
                            __half2* __restrict__ dstu,
                            const float* __restrict__ res32,
                            const __half* __restrict__ res16,
                            const float* __restrict__ srcimg,
                            const float* __restrict__ seg,
                            float* __restrict__ out) {
    int idx = blockIdx.x * blockDim.x + threadIdx.x;
    if (idx >= BHW) return;
    int x = idx & (Ww - 1);
    int y = (idx >> 9) & (Hh - 1);
    int base = idx - (y << 9) - x;
    float fx = (float)x, fy = (float)y;

    float2 ui = __half22float2(srcu[(size_t)i * BHW + idx]);
    float2 pd = make_float2(fx + ui.x, fy + ui.y);

    float acc = res32[(size_t)i * BHW + idx];
    float2 p0 = pd;

    for (int j = 0; j < i; j++) {
        float2 a = gather_phi(srcu + (size_t)j * BHW + base, pd.x, pd.y);
        dstu[(size_t)j * BHW + idx] = __floats2half2_rn(a.x - fx, a.y - fy);
        if (j == 0) p0 = a;
        else acc += gather_res16(res16 + (size_t)(j - 1) * BHW + base, a.x, a.y);
    }
    if (i >= 1) acc += gather_res16(res16 + (size_t)(i - 1) * BHW + base, pd.x, pd.y);

    float s = bilerp1(srcimg + base, p0.x, p0.y);
    float m = bilerp1(seg + base, p0.x, p0.y);
    const float scale = 2.5e-4f;  // MU^2 / L
    out[idx] = s + acc * scale * m;
}

extern "C" void kernel_launch(void* const* d_in, const int* in_sizes, int n_in,
                              void* d_out, int out_size) {
    const float* src = (const float*)d_in[0];
    const float* z0  = (const float*)d_in[1];
    const float* seg = (const float*)d_in[2];

    float*   res;   cudaGetSymbolAddress((void**)&res,   d_res);
    __half*  res16; cudaGetSymbolAddress((void**)&res16, d_res16);
    __half2* uA;    cudaGetSymbolAddress((void**)&uA,    d_uA);
    __half2* uB;    cudaGetSymbolAddress((void**)&uB,    d_uB);
    float*   img;   cudaGetSymbolAddress((void**)&img,   d_img);

    const int threads = 256;
    const int blocks = BHW / threads;
    dim3 vgrid(Ww / TX, Hh / TY, Bb);

    for (int i = 0; i < Lsteps; i++) {
        const float* img_in = (i == 0) ? src : img;
        const float* res_i  = (i == 0) ? z0  : res + (size_t)(i - 1) * BHW;

        k_vel<<<vgrid, 256>>>(img_in, res_i, res + (size_t)i * BHW,
                              res16 + (size_t)i * BHW,
                              uA + (size_t)i * BHW, uB + (size_t)i * BHW);

        __half2* dst = (i & 1) ? uB : uA;
        const __half2* s2 = (i & 1) ? uA : uB;
        float* outp = (i == Lsteps - 1) ? (float*)d_out : img;
        k_warpfinal<<<blocks, threads>>>(i, s2, dst, res, res16, src, seg, outp);
    }
}